// round 16
// baseline (speedup 1.0000x reference)
#include <cuda_runtime.h>
#include <cuda_bf16.h>
#include <cuda.h>
#include <cstdint>

// ---------------- problem constants ----------------
#define BATCH 4
#define NROIS 2048
#define CCH 256
#define HH 37
#define WW 37
#define HWSZ 1369
#define OUTS 7
#define NPTS 49
#define DFEAT 12544
#define HID 1024
#define NCLS 91

#if defined(__CUDA_ARCH_FEAT_SM103_ALL) || defined(__CUDA_ARCH_FEAT_SM100_ALL) || defined(__CUDA_ARCH_FEAT_SM101_ALL)
#define TC_PATH 1
#endif

// ---------------- scratch (device globals) ----------------
__device__ float g_T[BATCH * 4 * HWSZ * CCH];
__device__ __nv_bfloat16 g_Ahi[(size_t)NROIS * DFEAT];
__device__ __nv_bfloat16 g_Alo[(size_t)NROIS * DFEAT];
__device__ __nv_bfloat16 g_w1hi[(size_t)HID * DFEAT];
__device__ __nv_bfloat16 g_w1lo[(size_t)HID * DFEAT];
__device__ __nv_bfloat16 g_w2hi[(size_t)HID * HID];
__device__ __nv_bfloat16 g_w2lo[(size_t)HID * HID];
__device__ __nv_bfloat16 g_h1hi[(size_t)NROIS * HID];
__device__ __nv_bfloat16 g_h1lo[(size_t)NROIS * HID];
__device__ __nv_bfloat16 g_h2hi[(size_t)NROIS * HID];
__device__ __nv_bfloat16 g_h2lo[(size_t)NROIS * HID];
__device__ __nv_bfloat16 g_wcbhi[128 * HID];
__device__ __nv_bfloat16 g_wcblo[128 * HID];
__device__ float g_bcb[128];

// ---------------- PTX helpers ----------------
__device__ __forceinline__ uint32_t smem_u32(const void* p) {
    uint32_t a;
    asm("{ .reg .u64 t; cvta.to.shared.u64 t, %1; cvt.u32.u64 %0, t; }" : "=r"(a) : "l"(p));
    return a;
}
__device__ __forceinline__ uint32_t elect_one() {
    uint32_t pred;
    asm volatile("{\n\t.reg .pred p;\n\telect.sync _|p, 0xFFFFFFFF;\n\tselp.b32 %0, 1, 0, p;\n\t}"
                 : "=r"(pred));
    return pred;
}
#define MBAR_INIT(mbar, cnt) \
    asm volatile("mbarrier.init.shared.b64 [%0], %1;" :: "r"(mbar), "r"((uint32_t)(cnt)) : "memory")
#define MBAR_INVAL(mbar) \
    asm volatile("mbarrier.inval.shared.b64 [%0];" :: "r"(mbar) : "memory")
#define MBAR_EXPECT_TX(mbar, bytes) \
    asm volatile("mbarrier.arrive.expect_tx.shared.b64 _, [%0], %1;" \
                 :: "r"(mbar), "r"((uint32_t)(bytes)) : "memory")
#define MBAR_WAIT(mbar, parity) do { \
    uint32_t _m = (mbar); uint32_t _p = (parity); uint32_t _done; \
    asm volatile("{\n\t.reg .pred p;\n\t" \
        "mbarrier.try_wait.parity.acquire.cta.shared::cta.b64 p, [%1], %2;\n\t" \
        "selp.b32 %0, 1, 0, p;\n\t}" : "=r"(_done) : "r"(_m), "r"(_p) : "memory"); \
    if (!_done) { \
        asm volatile("{\n\t.reg .pred P1;\n\t" \
            "WL_%=:\n\t" \
            "mbarrier.try_wait.parity.acquire.cta.shared::cta.b64 P1, [%0], %1, 0x989680;\n\t" \
            "@P1 bra.uni WD_%=;\n\t" \
            "bra.uni WL_%=;\n\t" \
            "WD_%=:\n\t}" :: "r"(_m), "r"(_p) : "memory"); \
    } } while (0)

#ifdef TC_PATH
#define TC_ALLOC(smem_addr, n) \
    asm volatile("tcgen05.alloc.cta_group::1.sync.aligned.shared::cta.b32 [%0], %1;" \
                 :: "r"(smem_addr), "r"((uint32_t)(n)) : "memory")
#define TC_DEALLOC(tmem, n) \
    asm volatile("tcgen05.dealloc.cta_group::1.sync.aligned.b32 %0, %1;" :: "r"(tmem), "r"((uint32_t)(n)))
#define TC_RELINQ() \
    asm volatile("tcgen05.relinquish_alloc_permit.cta_group::1.sync.aligned;")
#define TC_ALLOC_CG2(smem_addr, n) \
    asm volatile("tcgen05.alloc.cta_group::2.sync.aligned.shared::cta.b32 [%0], %1;" \
                 :: "r"(smem_addr), "r"((uint32_t)(n)) : "memory")
#define TC_DEALLOC_CG2(tmem, n) \
    asm volatile("tcgen05.dealloc.cta_group::2.sync.aligned.b32 %0, %1;" :: "r"(tmem), "r"((uint32_t)(n)))
#define TC_RELINQ_CG2() \
    asm volatile("tcgen05.relinquish_alloc_permit.cta_group::2.sync.aligned;")
#define TC_COMMIT(mbar) \
    asm volatile("tcgen05.commit.cta_group::1.mbarrier::arrive::one.shared::cluster.b64 [%0];" \
                 :: "r"(mbar) : "memory")
#define TC_COMMIT_MC_CG2(mbar, mask) \
    asm volatile("tcgen05.commit.cta_group::2.mbarrier::arrive::one.shared::cluster.multicast::cluster.b64 [%0], %1;" \
                 :: "r"(mbar), "h"((uint16_t)(mask)) : "memory")
#define TC_FENCE_AFTER() asm volatile("tcgen05.fence::after_thread_sync;" ::: "memory")
#define TC_WAIT_LD() asm volatile("tcgen05.wait::ld.sync.aligned;" ::: "memory")
#define TMA_LD2D(smem, map, x, y, mbar) \
    asm volatile("cp.async.bulk.tensor.2d.shared::cta.global.tile.mbarrier::complete_tx::bytes " \
                 "[%0], [%1, {%2, %3}], [%4];" \
                 :: "r"(smem), "l"(map), "r"(x), "r"(y), "r"(mbar) : "memory")
#define TMA_LD2D_CG2(smem, map, x, y, mbar) \
    asm volatile("{\n\t.reg .b32 lb;\n\tand.b32 lb, %4, 0xFEFFFFFF;\n\t" \
                 "cp.async.bulk.tensor.2d.cta_group::2.shared::cluster.global.tile.mbarrier::complete_tx::bytes " \
                 "[%0], [%1, {%2, %3}], [lb];\n\t}" \
                 :: "r"(smem), "l"(map), "r"(x), "r"(y), "r"(mbar) : "memory")
#define CLUSTER_SYNC() do { \
    asm volatile("barrier.cluster.arrive.aligned;" ::: "memory"); \
    asm volatile("barrier.cluster.wait.aligned;" ::: "memory"); } while (0)
#define TC_LD_X32(r, tmem_addr) \
    asm volatile("tcgen05.ld.sync.aligned.32x32b.x32.b32 " \
        "{%0, %1, %2, %3, %4, %5, %6, %7, %8, %9, %10, %11, %12, %13, %14, %15, " \
        " %16, %17, %18, %19, %20, %21, %22, %23, %24, %25, %26, %27, %28, %29, %30, %31}, [%32];" \
        : "=r"((r)[0]),  "=r"((r)[1]),  "=r"((r)[2]),  "=r"((r)[3]), \
          "=r"((r)[4]),  "=r"((r)[5]),  "=r"((r)[6]),  "=r"((r)[7]), \
          "=r"((r)[8]),  "=r"((r)[9]),  "=r"((r)[10]), "=r"((r)[11]), \
          "=r"((r)[12]), "=r"((r)[13]), "=r"((r)[14]), "=r"((r)[15]), \
          "=r"((r)[16]), "=r"((r)[17]), "=r"((r)[18]), "=r"((r)[19]), \
          "=r"((r)[20]), "=r"((r)[21]), "=r"((r)[22]), "=r"((r)[23]), \
          "=r"((r)[24]), "=r"((r)[25]), "=r"((r)[26]), "=r"((r)[27]), \
          "=r"((r)[28]), "=r"((r)[29]), "=r"((r)[30]), "=r"((r)[31]) \
        : "r"(tmem_addr))

static __device__ __forceinline__ uint64_t make_desc_sw128(uint32_t addr) {
    constexpr uint64_t BASE =
        (uint64_t(2) << 61) | (uint64_t(1) << 46) | (uint64_t(64) << 32) | (uint64_t(1) << 16);
    return BASE | ((uint64_t)(addr >> 4) & 0x3FFF);
}
__device__ __forceinline__ void mma_f16_ss_cg1(uint32_t d, uint64_t a, uint64_t b,
                                               uint32_t idesc, bool accum) {
    uint32_t en = accum ? 1u : 0u;
    asm volatile(
        "{\n\t.reg .pred p;\n\tsetp.ne.u32 p, %5, 0;\n\t"
        "tcgen05.mma.cta_group::1.kind::f16 [%0], %1, %2, %3, {%4, %4, %4, %4}, p;\n\t}"
        :: "r"(d), "l"(a), "l"(b), "r"(idesc), "r"(0u), "r"(en) : "memory");
}
__device__ __forceinline__ void mma_f16_ss_cg2(uint32_t d, uint64_t a, uint64_t b,
                                               uint32_t idesc, bool accum) {
    uint32_t en = accum ? 1u : 0u;
    asm volatile(
        "{\n\t.reg .pred p;\n\tsetp.ne.u32 p, %6, 0;\n\t"
        "tcgen05.mma.cta_group::2.kind::f16 [%0], %1, %2, %3, "
        "{%4, %4, %4, %4, %4, %4, %4, %4}, p;\n\t}"
        :: "r"(d), "l"(a), "l"(b), "r"(idesc), "r"(0u), "r"(0u), "r"(en) : "memory");
}
#endif // TC_PATH

// ---------------- 1) feature transpose: scalar loads (HWSZ odd), float4 stores ----
__global__ void __launch_bounds__(256) transpose_feats(
    const float* __restrict__ f0, const float* __restrict__ f1,
    const float* __restrict__ f2, const float* __restrict__ f3) {
    __shared__ float tile[32][132];
    int bl = blockIdx.z;
    int b = bl >> 2, l = bl & 3;
    const float* f = (l == 0) ? f0 : (l == 1) ? f1 : (l == 2) ? f2 : f3;
    int hw0 = blockIdx.x * 128;
    int c0 = blockIdx.y * 32;
    int tid = threadIdx.x;

    int q = tid & 31;
    int cl = tid >> 5;
    #pragma unroll
    for (int it = 0; it < 4; it++) {
        int c = cl + it * 8;
        const float* src = f + ((size_t)b * CCH + c0 + c) * HWSZ;
        #pragma unroll
        for (int j = 0; j < 4; j++) {
            int hw = hw0 + q + j * 32;
            tile[c][q + j * 32] = (hw < HWSZ) ? src[hw] : 0.0f;
        }
    }
    __syncthreads();

    int c4g = tid & 7;
    int hwl = tid >> 3;
    #pragma unroll
    for (int it = 0; it < 4; it++) {
        int hw = hwl + it * 32;
        if (hw0 + hw < HWSZ) {
            float4 v;
            v.x = tile[c4g * 4 + 0][hw];
            v.y = tile[c4g * 4 + 1][hw];
            v.z = tile[c4g * 4 + 2][hw];
            v.w = tile[c4g * 4 + 3][hw];
            *reinterpret_cast<float4*>(
                g_T + ((size_t)bl * HWSZ + hw0 + hw) * CCH + c0 + c4g * 4) = v;
        }
    }
}

// ---------------- weight-split kernels ----------------
__global__ void split_w1(const float* __restrict__ w1) {
    __shared__ float tile[32][33];
    int k0 = blockIdx.x * 32;
    int n0 = blockIdx.y * 32;
    int k = k0 + threadIdx.y;
    int p = k >> 8, c = k & 255;
    int d = c * NPTS + p;
    tile[threadIdx.y][threadIdx.x] = w1[(size_t)d * HID + n0 + threadIdx.x];
    __syncthreads();
    float v = tile[threadIdx.x][threadIdx.y];
    __nv_bfloat16 hi = __float2bfloat16(v);
    __nv_bfloat16 lo = __float2bfloat16(v - __bfloat162float(hi));
    size_t o = (size_t)(n0 + threadIdx.y) * DFEAT + k0 + threadIdx.x;
    g_w1hi[o] = hi;
    g_w1lo[o] = lo;
}

__global__ void split_w2(const float* __restrict__ w2) {
    __shared__ float tile[32][33];
    int k0 = blockIdx.x * 32;
    int n0 = blockIdx.y * 32;
    tile[threadIdx.y][threadIdx.x] = w2[(size_t)(k0 + threadIdx.y) * HID + n0 + threadIdx.x];
    __syncthreads();
    float v = tile[threadIdx.x][threadIdx.y];
    __nv_bfloat16 hi = __float2bfloat16(v);
    __nv_bfloat16 lo = __float2bfloat16(v - __bfloat162float(hi));
    size_t o = (size_t)(n0 + threadIdx.y) * HID + k0 + threadIdx.x;
    g_w2hi[o] = hi;
    g_w2lo[o] = lo;
}

__global__ void split_wcb(const float* __restrict__ wc, const float* __restrict__ wb,
                          const float* __restrict__ bc, const float* __restrict__ bb) {
    __shared__ float tile[32][33];
    int k0 = blockIdx.x * 32;
    int n0 = blockIdx.y * 32;
    int k = k0 + threadIdx.y;
    int n = n0 + threadIdx.x;
    float v = 0.0f;
    if (n < NCLS) v = wc[(size_t)k * NCLS + n];
    else if (n < NCLS + 4) v = wb[(size_t)k * 4 + (n - NCLS)];
    tile[threadIdx.y][threadIdx.x] = v;
    if (blockIdx.x == 0 && threadIdx.y == 0) {
        int j = n0 + threadIdx.x;
        g_bcb[j] = (j < NCLS) ? bc[j] : ((j < NCLS + 4) ? bb[j - NCLS] : 0.0f);
    }
    __syncthreads();
    float u = tile[threadIdx.x][threadIdx.y];
    __nv_bfloat16 hi = __float2bfloat16(u);
    __nv_bfloat16 lo = __float2bfloat16(u - __bfloat162float(hi));
    size_t o = (size_t)(n0 + threadIdx.y) * HID + k0 + threadIdx.x;
    g_wcbhi[o] = hi;
    g_wcblo[o] = lo;
}

// ---------------- multilevel ROI align: smem-precomputed taps, 512 threads ----------
// Coordinate math (clip/floor/weights/offsets) is computed ONCE per (point,sample) by
// 196 threads into smem; the main loop is a flat 16-tap LDS64+LDG128+FMA stream.
__global__ void __launch_bounds__(512) roi_align(const float* __restrict__ proposals) {
    __shared__ float2 s_tap[NPTS][16];   // {offset_as_float, weight} per bilinear tap

    int rid = blockIdx.x;
    int b = rid >> 9;
    int tid = threadIdx.x;
    int g = tid >> 6;            // point slot 0..7
    int c4 = (tid & 63) * 4;     // channel base

    float px1 = proposals[rid * 4 + 0];
    float py1 = proposals[rid * 4 + 1];
    float px2 = proposals[rid * 4 + 2];
    float py2 = proposals[rid * 4 + 3];
    float bw = px2 - px1, bh = py2 - py1;
    float area = bw * bh;
    int lvl = (area >= 1024.0f) + (area >= 4096.0f) + (area >= 16384.0f);
    float x1 = px1 - 0.5f, y1 = py1 - 0.5f;
    float binw = bw / 7.0f, binh = bh / 7.0f;

    // --- precompute: thread t < 196 handles (p = t/4, s = t%4) -> 4 taps
    if (tid < NPTS * 4) {
        int p = tid >> 2, s = tid & 3;
        int oy = p / OUTS, ox = p % OUTS;
        int sy = s >> 1, sx = s & 1;
        float y = y1 + ((float)oy + ((float)sy + 0.5f) * 0.5f) * binh;
        float x = x1 + ((float)ox + ((float)sx + 0.5f) * 0.5f) * binw;
        float2* dst = &s_tap[p][s * 4];
        if (y < -1.0f || y > (float)HH || x < -1.0f || x > (float)WW) {
            dst[0] = make_float2(__int_as_float(0), 0.0f);
            dst[1] = make_float2(__int_as_float(0), 0.0f);
            dst[2] = make_float2(__int_as_float(0), 0.0f);
            dst[3] = make_float2(__int_as_float(0), 0.0f);
        } else {
            float yc = fminf(fmaxf(y, 0.0f), (float)(HH - 1));
            float xc = fminf(fmaxf(x, 0.0f), (float)(WW - 1));
            float y0f = floorf(yc), x0f = floorf(xc);
            int y0 = (int)y0f, x0 = (int)x0f;
            int y1i = min(y0 + 1, HH - 1), x1i = min(x0 + 1, WW - 1);
            float ly = yc - y0f, lx = xc - x0f;
            float hy = 1.0f - ly, hx = 1.0f - lx;
            dst[0] = make_float2(__int_as_float((y0  * WW + x0 ) * CCH), hy * hx);
            dst[1] = make_float2(__int_as_float((y0  * WW + x1i) * CCH), hy * lx);
            dst[2] = make_float2(__int_as_float((y1i * WW + x0 ) * CCH), ly * hx);
            dst[3] = make_float2(__int_as_float((y1i * WW + x1i) * CCH), ly * lx);
        }
    }
    __syncthreads();

    const float* Tb = g_T + ((size_t)(b * 4 + lvl) * HWSZ) * CCH + c4;
    size_t dbase = (size_t)rid * DFEAT;

    #pragma unroll 1
    for (int p0 = 0; p0 < NPTS; p0 += 8) {
        int p = p0 + g;
        if (p >= NPTS) break;    // warp-uniform (g constant per warp)
        const float2* tp = s_tap[p];
        float ax = 0.f, ay = 0.f, az = 0.f, aw = 0.f;
        #pragma unroll
        for (int t = 0; t < 16; t++) {
            float2 ow = tp[t];           // broadcast LDS.64
            int off = __float_as_int(ow.x);
            float w = ow.y;
            float4 v = *reinterpret_cast<const float4*>(Tb + off);
            ax = fmaf(w, v.x, ax);
            ay = fmaf(w, v.y, ay);
            az = fmaf(w, v.z, az);
            aw = fmaf(w, v.w, aw);
        }
        float r[4] = {ax * 0.25f, ay * 0.25f, az * 0.25f, aw * 0.25f};
        __nv_bfloat16 h[4], l[4];
        #pragma unroll
        for (int i = 0; i < 4; i++) {
            h[i] = __float2bfloat16(r[i]);
            l[i] = __float2bfloat16(r[i] - __bfloat162float(h[i]));
        }
        uint2 hp, lp;
        hp.x = ((uint32_t)__bfloat16_as_ushort(h[1]) << 16) | __bfloat16_as_ushort(h[0]);
        hp.y = ((uint32_t)__bfloat16_as_ushort(h[3]) << 16) | __bfloat16_as_ushort(h[2]);
        lp.x = ((uint32_t)__bfloat16_as_ushort(l[1]) << 16) | __bfloat16_as_ushort(l[0]);
        lp.y = ((uint32_t)__bfloat16_as_ushort(l[3]) << 16) | __bfloat16_as_ushort(l[2]);
        *reinterpret_cast<uint2*>(&g_Ahi[dbase + p * CCH + c4]) = hp;
        *reinterpret_cast<uint2*>(&g_Alo[dbase + p * CCH + c4]) = lp;
    }
}

// ---------------- cg2 TMA-pipelined GEMM (proven) ----------------
#define KC 64
#define ST2 4
#define STB2 49152
#define SM_TMEMP 0
#define SM2_FULL 8
#define SM2_EMPTY (8 + ST2 * 8)
#define SM_TILES 1024
#define GEMM_SMEM (SM_TILES + ST2 * STB2)

__global__ void __launch_bounds__(256) __cluster_dims__(2, 1, 1) gemm_cg2(
    const __grid_constant__ CUtensorMap tmAhi, const __grid_constant__ CUtensorMap tmAlo,
    const __grid_constant__ CUtensorMap tmBhi, const __grid_constant__ CUtensorMap tmBlo,
    const float* __restrict__ bias, int K,
    __nv_bfloat16* __restrict__ outHi, __nv_bfloat16* __restrict__ outLo, int Nfull) {
#ifdef TC_PATH
    constexpr uint32_t IDESC =
        (1u << 4) | (1u << 7) | (1u << 10) | ((128 / 8) << 17) | ((256 / 16) << 24);

    extern __shared__ char smem[];
    uint32_t sb = smem_u32(smem);
    const int tid = threadIdx.x;
    const int wid = tid >> 5, lane = tid & 31;
    const int m0 = blockIdx.x * 128;
    const int n0 = blockIdx.y * 128;
    const uint32_t rank = blockIdx.x & 1;

    if (wid == 0) TC_ALLOC_CG2(sb + SM_TMEMP, 128);
    if (tid == 0) {
        #pragma unroll
        for (int s = 0; s < ST2; s++) {
            MBAR_INIT(sb + SM2_FULL + s * 8, 1);
            MBAR_INIT(sb + SM2_EMPTY + s * 8, 1);
        }
    }
    __syncthreads();
    CLUSTER_SYNC();
    uint32_t tmem;
    asm volatile("ld.shared.b32 %0, [%1];" : "=r"(tmem) : "r"(sb + SM_TMEMP));

    const int NCH = K / KC;

    if (wid == 0) {
        uint32_t el = elect_one();
        auto issue = [&](int j) {
            int s = j % ST2;
            if (j >= ST2) MBAR_WAIT(sb + SM2_EMPTY + s * 8, ((j / ST2) - 1) & 1);
            if (el) {
                uint32_t st = sb + SM_TILES + s * STB2;
                uint32_t fb = sb + SM2_FULL + s * 8;
                if (rank == 0) MBAR_EXPECT_TX(fb, 2 * STB2);
                TMA_LD2D_CG2(st,         &tmAhi, j * KC, m0, fb);
                TMA_LD2D_CG2(st + 16384, &tmAlo, j * KC, m0, fb);
                TMA_LD2D_CG2(st + 32768, &tmBhi, j * KC, n0 + (int)rank * 64, fb);
                TMA_LD2D_CG2(st + 40960, &tmBlo, j * KC, n0 + (int)rank * 64, fb);
            }
        };
        issue(0);
        if (NCH > 1) issue(1);
        if (NCH > 2) issue(2);
        #pragma unroll 1
        for (int j = 0; j < NCH; j++) {
            if (rank == 0) {
                int s = j % ST2;
                MBAR_WAIT(sb + SM2_FULL + s * 8, (j / ST2) & 1);
                if (el) {
                    uint32_t st = sb + SM_TILES + s * STB2;
                    uint64_t adh = make_desc_sw128(st);
                    uint64_t adl = make_desc_sw128(st + 16384);
                    uint64_t bdh = make_desc_sw128(st + 32768);
                    uint64_t bdl = make_desc_sw128(st + 40960);
                    #pragma unroll
                    for (int ks = 0; ks < 4; ks++)
                        mma_f16_ss_cg2(tmem, adh + ks * 2, bdh + ks * 2, IDESC, (j > 0) || (ks > 0));
                    #pragma unroll
                    for (int ks = 0; ks < 4; ks++)
                        mma_f16_ss_cg2(tmem, adl + ks * 2, bdh + ks * 2, IDESC, true);
                    #pragma unroll
                    for (int ks = 0; ks < 4; ks++)
                        mma_f16_ss_cg2(tmem, adh + ks * 2, bdl + ks * 2, IDESC, true);
                    TC_COMMIT_MC_CG2(sb + SM2_EMPTY + s * 8, 0x3);
                }
            }
            if (j + 3 < NCH) issue(j + 3);
        }
        MBAR_WAIT(sb + SM2_EMPTY + ((NCH - 1) % ST2) * 8, ((NCH - 1) / ST2) & 1);
    }
    __syncthreads();
    TC_FENCE_AFTER();

    int m = m0 + (wid & 3) * 32 + lane;
    int colbase = (wid >> 2) * 64;
    #pragma unroll
    for (int jb = 0; jb < 2; jb++) {
        int coloff = colbase + jb * 32;
        uint32_t r[32];
        TC_LD_X32(r, tmem + coloff);
        TC_WAIT_LD();
        #pragma unroll
        for (int c = 0; c < 32; c += 2) {
            int n = n0 + coloff + c;
            float v0 = fmaxf(__uint_as_float(r[c]) + bias[n], 0.0f);
            float v1 = fmaxf(__uint_as_float(r[c + 1]) + bias[n + 1], 0.0f);
            __nv_bfloat16 h0 = __float2bfloat16(v0);
            __nv_bfloat16 h1 = __float2bfloat16(v1);
            __nv_bfloat16 l0 = __float2bfloat16(v0 - __bfloat162float(h0));
            __nv_bfloat16 l1 = __float2bfloat16(v1 - __bfloat162float(h1));
            __nv_bfloat162 hp; hp.x = h0; hp.y = h1;
            __nv_bfloat162 lp; lp.x = l0; lp.y = l1;
            *reinterpret_cast<__nv_bfloat162*>(outHi + (size_t)m * Nfull + n) = hp;
            *reinterpret_cast<__nv_bfloat162*>(outLo + (size_t)m * Nfull + n) = lp;
        }
    }

    __syncthreads();
    if (tid == 0) {
        #pragma unroll
        for (int s = 0; s < ST2; s++) {
            MBAR_INVAL(sb + SM2_FULL + s * 8);
            MBAR_INVAL(sb + SM2_EMPTY + s * 8);
        }
    }
    __syncthreads();
    if (wid == 0) {
        TC_RELINQ_CG2();
        TC_DEALLOC_CG2(tmem, 128);
    }
    CLUSTER_SYNC();
#endif
}

// ---------------- cg1 GEMM for the heads ----------------
#define ST1 3
#define STB1 65536
#define SM1_FULL 8
#define SM1_EMPTY (8 + ST1 * 8)

__global__ void __launch_bounds__(256) gemm_heads(
    const __grid_constant__ CUtensorMap tmAhi, const __grid_constant__ CUtensorMap tmAlo,
    const __grid_constant__ CUtensorMap tmBhi, const __grid_constant__ CUtensorMap tmBlo,
    const float* __restrict__ bias, int K,
    float* __restrict__ outScores, float* __restrict__ outBbox) {
#ifdef TC_PATH
    constexpr uint32_t IDESC =
        (1u << 4) | (1u << 7) | (1u << 10) | ((128 / 8) << 17) | (8u << 24);

    extern __shared__ char smem[];
    uint32_t sb = smem_u32(smem);
    const int tid = threadIdx.x;
    const int wid = tid >> 5, lane = tid & 31;
    const int m0 = blockIdx.y * 128;
    const int n0 = blockIdx.x * 128;

    if (wid == 0) TC_ALLOC(sb + SM_TMEMP, 128);
    if (tid == 0) {
        #pragma unroll
        for (int s = 0; s < ST1; s++) {
            MBAR_INIT(sb + SM1_FULL + s * 8, 1);
            MBAR_INIT(sb + SM1_EMPTY + s * 8, 1);
        }
    }
    __syncthreads();
    uint32_t tmem;
    asm volatile("ld.shared.b32 %0, [%1];" : "=r"(tmem) : "r"(sb + SM_TMEMP));

    const int NCH = K / KC;

    if (wid == 0) {
        uint32_t el = elect_one();
        auto issue = [&](int j) {
            int s = j % ST1;
            if (j >= ST1) MBAR_WAIT(sb + SM1_EMPTY + s * 8, ((j / ST1) - 1) & 1);
            if (el) {
                uint32_t st = sb + SM_TILES + s * STB1;
                uint32_t fb = sb + SM1_FULL + s * 8;
                MBAR_EXPECT_TX(fb, STB1);
                TMA_LD2D(st,         &tmAhi, j * KC, m0, fb);
                TMA_LD2D(st + 16384, &tmAlo, j * KC, m0, fb);
                TMA_LD2D(st + 32768, &tmBhi, j * KC, n0, fb);
                TMA_LD2D(st + 49152, &tmBlo, j * KC, n0, fb);
            }
        };
        issue(0);
        if (NCH > 1) issue(1);
        #pragma unroll 1
        for (int j = 0; j < NCH; j++) {
            int s = j % ST1;
            MBAR_WAIT(sb + SM1_FULL + s * 8, (j / ST1) & 1);
            if (el) {
                uint32_t st = sb + SM_TILES + s * STB1;
                uint64_t adh = make_desc_sw128(st);
                uint64_t adl = make_desc_sw128(st + 16384);
                uint64_t bdh = make_desc_sw128(st + 32768);
                uint64_t bdl = make_desc_sw128(st + 49152);
                #pragma unroll
                for (int ks = 0; ks < 4; ks++)
                    mma_f16_ss_cg1(tmem, adh + ks * 2, bdh + ks * 2, IDESC, (j > 0) || (ks > 0));
                #pragma unroll
                for (int ks = 0; ks < 4; ks++)
                    mma_f16_ss_cg1(tmem, adl + ks * 2, bdh + ks * 2, IDESC, true);
                #pragma unroll
                for (int ks = 0; ks < 4; ks++)
                    mma_f16_ss_cg1(tmem, adh + ks * 2, bdl + ks * 2, IDESC, true);
                TC_COMMIT(sb + SM1_EMPTY + s * 8);
            }
            if (j + 2 < NCH) issue(j + 2);
        }
        MBAR_WAIT(sb + SM1_EMPTY + ((NCH - 1) % ST1) * 8, ((NCH - 1) / ST1) & 1);
    }
    __syncthreads();
    TC_FENCE_AFTER();

    int m = m0 + (wid & 3) * 32 + lane;
    int colbase = (wid >> 2) * 64;
    #pragma unroll
    for (int jb = 0; jb < 2; jb++) {
        int coloff = colbase + jb * 32;
        uint32_t r[32];
        TC_LD_X32(r, tmem + coloff);
        TC_WAIT_LD();
        #pragma unroll
        for (int c = 0; c < 32; c++) {
            int n = n0 + coloff + c;
            float v = __uint_as_float(r[c]) + bias[n];
            if (n < NCLS) outScores[(size_t)m * NCLS + n] = v;
            else if (n < NCLS + 4) outBbox[(size_t)m * 4 + (n - NCLS)] = v;
        }
    }

    __syncthreads();
    if (tid == 0) {
        #pragma unroll
        for (int s = 0; s < ST1; s++) {
            MBAR_INVAL(sb + SM1_FULL + s * 8);
            MBAR_INVAL(sb + SM1_EMPTY + s * 8);
        }
    }
    __syncthreads();
    if (wid == 0) {
        TC_RELINQ();
        TC_DEALLOC(tmem, 128);
    }
#endif
}

// ---------------- host: tensormap encode ----------------
typedef CUresult (*tmEncodeFn)(CUtensorMap*, CUtensorMapDataType, cuuint32_t, void*,
                               const cuuint64_t*, const cuuint64_t*, const cuuint32_t*,
                               const cuuint32_t*, CUtensorMapInterleave, CUtensorMapSwizzle,
                               CUtensorMapL2promotion, CUtensorMapFloatOOBfill);

static void make_tm_bf16_2d(tmEncodeFn enc, CUtensorMap* tm, void* ptr,
                            uint64_t dim0, uint64_t dim1, uint32_t box1) {
    cuuint64_t dims[2] = {dim0, dim1};
    cuuint64_t strides[1] = {dim0 * 2};
    cuuint32_t box[2] = {64, box1};
    cuuint32_t es[2] = {1, 1};
    enc(tm, CU_TENSOR_MAP_DATA_TYPE_BFLOAT16, 2, ptr, dims, strides, box, es,
        CU_TENSOR_MAP_INTERLEAVE_NONE, CU_TENSOR_MAP_SWIZZLE_128B,
        CU_TENSOR_MAP_L2_PROMOTION_L2_128B, CU_TENSOR_MAP_FLOAT_OOB_FILL_NONE);
}

// ---------------- launch ----------------
extern "C" void kernel_launch(void* const* d_in, const int* in_sizes, int n_in,
                              void* d_out, int out_size) {
    const float* f0 = (const float*)d_in[0];
    const float* f1 = (const float*)d_in[1];
    const float* f2 = (const float*)d_in[2];
    const float* f3 = (const float*)d_in[3];
    const float* proposals = (const float*)d_in[4];
    const float* w1 = (const float*)d_in[5];
    const float* b1 = (const float*)d_in[6];
    const float* w2 = (const float*)d_in[7];
    const float* b2 = (const float*)d_in[8];
    const float* wc = (const float*)d_in[9];
    const float* bc = (const float*)d_in[10];
    const float* wb = (const float*)d_in[11];
    const float* bb = (const float*)d_in[12];

    float* out_scores = (float*)d_out;
    float* out_bbox = (float*)d_out + (size_t)NROIS * NCLS;

    void *gAhi, *gAlo, *gW1hi, *gW1lo, *gW2hi, *gW2lo;
    void *gH1hi, *gH1lo, *gH2hi, *gH2lo, *gWcbhi, *gWcblo, *gBcb;
    cudaGetSymbolAddress(&gAhi, g_Ahi);
    cudaGetSymbolAddress(&gAlo, g_Alo);
    cudaGetSymbolAddress(&gW1hi, g_w1hi);
    cudaGetSymbolAddress(&gW1lo, g_w1lo);
    cudaGetSymbolAddress(&gW2hi, g_w2hi);
    cudaGetSymbolAddress(&gW2lo, g_w2lo);
    cudaGetSymbolAddress(&gH1hi, g_h1hi);
    cudaGetSymbolAddress(&gH1lo, g_h1lo);
    cudaGetSymbolAddress(&gH2hi, g_h2hi);
    cudaGetSymbolAddress(&gH2lo, g_h2lo);
    cudaGetSymbolAddress(&gWcbhi, g_wcbhi);
    cudaGetSymbolAddress(&gWcblo, g_wcblo);
    cudaGetSymbolAddress(&gBcb, g_bcb);

    void* fn = nullptr;
    cudaDriverEntryPointQueryResult qr;
    cudaGetDriverEntryPoint("cuTensorMapEncodeTiled", &fn, cudaEnableDefault, &qr);
    tmEncodeFn enc = (tmEncodeFn)fn;

    CUtensorMap tAhi1, tAlo1, tBhi1, tBlo1;
    CUtensorMap tAhi2, tAlo2, tBhi2, tBlo2;
    CUtensorMap tAhi3, tAlo3, tBhi3, tBlo3;
    make_tm_bf16_2d(enc, &tAhi1, gAhi, DFEAT, NROIS, 128);
    make_tm_bf16_2d(enc, &tAlo1, gAlo, DFEAT, NROIS, 128);
    make_tm_bf16_2d(enc, &tBhi1, gW1hi, DFEAT, HID, 64);
    make_tm_bf16_2d(enc, &tBlo1, gW1lo, DFEAT, HID, 64);
    make_tm_bf16_2d(enc, &tAhi2, gH1hi, HID, NROIS, 128);
    make_tm_bf16_2d(enc, &tAlo2, gH1lo, HID, NROIS, 128);
    make_tm_bf16_2d(enc, &tBhi2, gW2hi, HID, HID, 64);
    make_tm_bf16_2d(enc, &tBlo2, gW2lo, HID, HID, 64);
    make_tm_bf16_2d(enc, &tAhi3, gH2hi, HID, NROIS, 128);
    make_tm_bf16_2d(enc, &tAlo3, gH2lo, HID, NROIS, 128);
    make_tm_bf16_2d(enc, &tBhi3, gWcbhi, HID, 128, 128);
    make_tm_bf16_2d(enc, &tBlo3, gWcblo, HID, 128, 128);

    cudaFuncSetAttribute(gemm_cg2, cudaFuncAttributeMaxDynamicSharedMemorySize, GEMM_SMEM);
    cudaFuncSetAttribute(gemm_heads, cudaFuncAttributeMaxDynamicSharedMemorySize, GEMM_SMEM);

    static cudaStream_t s_side = nullptr;
    static cudaEvent_t evFork = nullptr, evW1 = nullptr, evW2 = nullptr, evWcb = nullptr;
    if (!s_side) {
        cudaStreamCreateWithFlags(&s_side, cudaStreamNonBlocking);
        cudaEventCreateWithFlags(&evFork, cudaEventDisableTiming);
        cudaEventCreateWithFlags(&evW1, cudaEventDisableTiming);
        cudaEventCreateWithFlags(&evW2, cudaEventDisableTiming);
        cudaEventCreateWithFlags(&evWcb, cudaEventDisableTiming);
    }

    // fork: weight-prep on side stream; roi_align stays launch #4 for ncu continuity
    cudaEventRecord(evFork, 0);
    cudaStreamWaitEvent(s_side, evFork, 0);

    split_w1<<<dim3(DFEAT / 32, HID / 32), dim3(32, 32), 0, s_side>>>(w1);      // #1
    cudaEventRecord(evW1, s_side);
    split_w2<<<dim3(HID / 32, HID / 32), dim3(32, 32), 0, s_side>>>(w2);        // #2
    cudaEventRecord(evW2, s_side);

    {
        dim3 grid((HWSZ + 127) / 128, CCH / 32, BATCH * 4);
        transpose_feats<<<grid, 256>>>(f0, f1, f2, f3);                          // #3
    }
    roi_align<<<NROIS, 512>>>(proposals);                                        // #4

    split_wcb<<<dim3(HID / 32, 4), dim3(32, 32), 0, s_side>>>(wc, wb, bc, bb);   // #5
    cudaEventRecord(evWcb, s_side);

    cudaLaunchConfig_t cfg = {};
    cudaLaunchAttribute at[1];
    at[0].id = cudaLaunchAttributeClusterDimension;
    at[0].val.clusterDim = {2, 1, 1};
    cfg.attrs = at;
    cfg.numAttrs = 1;
    cfg.blockDim = dim3(256, 1, 1);
    cfg.dynamicSmemBytes = GEMM_SMEM;
    cfg.gridDim = dim3(NROIS / 128, HID / 128);

    cudaStreamWaitEvent(0, evW1, 0);
    cudaLaunchKernelEx(&cfg, gemm_cg2,
                       tAhi1, tAlo1, tBhi1, tBlo1, (const float*)b1, (int)DFEAT,
                       (__nv_bfloat16*)gH1hi, (__nv_bfloat16*)gH1lo, (int)HID);

    cudaStreamWaitEvent(0, evW2, 0);
    cudaLaunchKernelEx(&cfg, gemm_cg2,
                       tAhi2, tAlo2, tBhi2, tBlo2, (const float*)b2, (int)HID,
                       (__nv_bfloat16*)gH2hi, (__nv_bfloat16*)gH2lo, (int)HID);

    cudaStreamWaitEvent(0, evWcb, 0);
    gemm_heads<<<dim3(1, NROIS / 128), 256, GEMM_SMEM>>>(
        tAhi3, tAlo3, tBhi3, tBlo3, (const float*)gBcb, HID, out_scores, out_bbox);
}

// round 17
// speedup vs baseline: 1.1930x; 1.1930x over previous
#include <cuda_runtime.h>
#include <cuda_bf16.h>
#include <cuda.h>
#include <cstdint>

// ---------------- problem constants ----------------
#define BATCH 4
#define NROIS 2048
#define CCH 256
#define HH 37
#define WW 37
#define HWSZ 1369
#define OUTS 7
#define NPTS 49
#define DFEAT 12544
#define HID 1024
#define NCLS 91

#if defined(__CUDA_ARCH_FEAT_SM103_ALL) || defined(__CUDA_ARCH_FEAT_SM100_ALL) || defined(__CUDA_ARCH_FEAT_SM101_ALL)
#define TC_PATH 1
#endif

// ---------------- scratch (device globals) ----------------
__device__ float g_T[BATCH * 4 * HWSZ * CCH];
__device__ __nv_bfloat16 g_Ahi[(size_t)NROIS * DFEAT];
__device__ __nv_bfloat16 g_Alo[(size_t)NROIS * DFEAT];
__device__ __nv_bfloat16 g_w1hi[(size_t)HID * DFEAT];
__device__ __nv_bfloat16 g_w1lo[(size_t)HID * DFEAT];
__device__ __nv_bfloat16 g_w2hi[(size_t)HID * HID];
__device__ __nv_bfloat16 g_w2lo[(size_t)HID * HID];
__device__ __nv_bfloat16 g_h1hi[(size_t)NROIS * HID];
__device__ __nv_bfloat16 g_h1lo[(size_t)NROIS * HID];
__device__ __nv_bfloat16 g_h2hi[(size_t)NROIS * HID];
__device__ __nv_bfloat16 g_h2lo[(size_t)NROIS * HID];
__device__ __nv_bfloat16 g_wcbhi[128 * HID];
__device__ __nv_bfloat16 g_wcblo[128 * HID];
__device__ float g_bcb[128];

// ---------------- PTX helpers ----------------
__device__ __forceinline__ uint32_t smem_u32(const void* p) {
    uint32_t a;
    asm("{ .reg .u64 t; cvta.to.shared.u64 t, %1; cvt.u32.u64 %0, t; }" : "=r"(a) : "l"(p));
    return a;
}
__device__ __forceinline__ uint32_t elect_one() {
    uint32_t pred;
    asm volatile("{\n\t.reg .pred p;\n\telect.sync _|p, 0xFFFFFFFF;\n\tselp.b32 %0, 1, 0, p;\n\t}"
                 : "=r"(pred));
    return pred;
}
#define MBAR_INIT(mbar, cnt) \
    asm volatile("mbarrier.init.shared.b64 [%0], %1;" :: "r"(mbar), "r"((uint32_t)(cnt)) : "memory")
#define MBAR_INVAL(mbar) \
    asm volatile("mbarrier.inval.shared.b64 [%0];" :: "r"(mbar) : "memory")
#define MBAR_EXPECT_TX(mbar, bytes) \
    asm volatile("mbarrier.arrive.expect_tx.shared.b64 _, [%0], %1;" \
                 :: "r"(mbar), "r"((uint32_t)(bytes)) : "memory")
#define MBAR_WAIT(mbar, parity) do { \
    uint32_t _m = (mbar); uint32_t _p = (parity); uint32_t _done; \
    asm volatile("{\n\t.reg .pred p;\n\t" \
        "mbarrier.try_wait.parity.acquire.cta.shared::cta.b64 p, [%1], %2;\n\t" \
        "selp.b32 %0, 1, 0, p;\n\t}" : "=r"(_done) : "r"(_m), "r"(_p) : "memory"); \
    if (!_done) { \
        asm volatile("{\n\t.reg .pred P1;\n\t" \
            "WL_%=:\n\t" \
            "mbarrier.try_wait.parity.acquire.cta.shared::cta.b64 P1, [%0], %1, 0x989680;\n\t" \
            "@P1 bra.uni WD_%=;\n\t" \
            "bra.uni WL_%=;\n\t" \
            "WD_%=:\n\t}" :: "r"(_m), "r"(_p) : "memory"); \
    } } while (0)

#ifdef TC_PATH
#define TC_ALLOC(smem_addr, n) \
    asm volatile("tcgen05.alloc.cta_group::1.sync.aligned.shared::cta.b32 [%0], %1;" \
                 :: "r"(smem_addr), "r"((uint32_t)(n)) : "memory")
#define TC_DEALLOC(tmem, n) \
    asm volatile("tcgen05.dealloc.cta_group::1.sync.aligned.b32 %0, %1;" :: "r"(tmem), "r"((uint32_t)(n)))
#define TC_RELINQ() \
    asm volatile("tcgen05.relinquish_alloc_permit.cta_group::1.sync.aligned;")
#define TC_ALLOC_CG2(smem_addr, n) \
    asm volatile("tcgen05.alloc.cta_group::2.sync.aligned.shared::cta.b32 [%0], %1;" \
                 :: "r"(smem_addr), "r"((uint32_t)(n)) : "memory")
#define TC_DEALLOC_CG2(tmem, n) \
    asm volatile("tcgen05.dealloc.cta_group::2.sync.aligned.b32 %0, %1;" :: "r"(tmem), "r"((uint32_t)(n)))
#define TC_RELINQ_CG2() \
    asm volatile("tcgen05.relinquish_alloc_permit.cta_group::2.sync.aligned;")
#define TC_COMMIT(mbar) \
    asm volatile("tcgen05.commit.cta_group::1.mbarrier::arrive::one.shared::cluster.b64 [%0];" \
                 :: "r"(mbar) : "memory")
#define TC_COMMIT_MC_CG2(mbar, mask) \
    asm volatile("tcgen05.commit.cta_group::2.mbarrier::arrive::one.shared::cluster.multicast::cluster.b64 [%0], %1;" \
                 :: "r"(mbar), "h"((uint16_t)(mask)) : "memory")
#define TC_FENCE_AFTER() asm volatile("tcgen05.fence::after_thread_sync;" ::: "memory")
#define TC_WAIT_LD() asm volatile("tcgen05.wait::ld.sync.aligned;" ::: "memory")
#define TMA_LD2D(smem, map, x, y, mbar) \
    asm volatile("cp.async.bulk.tensor.2d.shared::cta.global.tile.mbarrier::complete_tx::bytes " \
                 "[%0], [%1, {%2, %3}], [%4];" \
                 :: "r"(smem), "l"(map), "r"(x), "r"(y), "r"(mbar) : "memory")
#define TMA_LD2D_CG2(smem, map, x, y, mbar) \
    asm volatile("{\n\t.reg .b32 lb;\n\tand.b32 lb, %4, 0xFEFFFFFF;\n\t" \
                 "cp.async.bulk.tensor.2d.cta_group::2.shared::cluster.global.tile.mbarrier::complete_tx::bytes " \
                 "[%0], [%1, {%2, %3}], [lb];\n\t}" \
                 :: "r"(smem), "l"(map), "r"(x), "r"(y), "r"(mbar) : "memory")
#define CLUSTER_SYNC() do { \
    asm volatile("barrier.cluster.arrive.aligned;" ::: "memory"); \
    asm volatile("barrier.cluster.wait.aligned;" ::: "memory"); } while (0)
#define TC_LD_X32(r, tmem_addr) \
    asm volatile("tcgen05.ld.sync.aligned.32x32b.x32.b32 " \
        "{%0, %1, %2, %3, %4, %5, %6, %7, %8, %9, %10, %11, %12, %13, %14, %15, " \
        " %16, %17, %18, %19, %20, %21, %22, %23, %24, %25, %26, %27, %28, %29, %30, %31}, [%32];" \
        : "=r"((r)[0]),  "=r"((r)[1]),  "=r"((r)[2]),  "=r"((r)[3]), \
          "=r"((r)[4]),  "=r"((r)[5]),  "=r"((r)[6]),  "=r"((r)[7]), \
          "=r"((r)[8]),  "=r"((r)[9]),  "=r"((r)[10]), "=r"((r)[11]), \
          "=r"((r)[12]), "=r"((r)[13]), "=r"((r)[14]), "=r"((r)[15]), \
          "=r"((r)[16]), "=r"((r)[17]), "=r"((r)[18]), "=r"((r)[19]), \
          "=r"((r)[20]), "=r"((r)[21]), "=r"((r)[22]), "=r"((r)[23]), \
          "=r"((r)[24]), "=r"((r)[25]), "=r"((r)[26]), "=r"((r)[27]), \
          "=r"((r)[28]), "=r"((r)[29]), "=r"((r)[30]), "=r"((r)[31]) \
        : "r"(tmem_addr))

static __device__ __forceinline__ uint64_t make_desc_sw128(uint32_t addr) {
    constexpr uint64_t BASE =
        (uint64_t(2) << 61) | (uint64_t(1) << 46) | (uint64_t(64) << 32) | (uint64_t(1) << 16);
    return BASE | ((uint64_t)(addr >> 4) & 0x3FFF);
}
__device__ __forceinline__ void mma_f16_ss_cg1(uint32_t d, uint64_t a, uint64_t b,
                                               uint32_t idesc, bool accum) {
    uint32_t en = accum ? 1u : 0u;
    asm volatile(
        "{\n\t.reg .pred p;\n\tsetp.ne.u32 p, %5, 0;\n\t"
        "tcgen05.mma.cta_group::1.kind::f16 [%0], %1, %2, %3, {%4, %4, %4, %4}, p;\n\t}"
        :: "r"(d), "l"(a), "l"(b), "r"(idesc), "r"(0u), "r"(en) : "memory");
}
__device__ __forceinline__ void mma_f16_ss_cg2(uint32_t d, uint64_t a, uint64_t b,
                                               uint32_t idesc, bool accum) {
    uint32_t en = accum ? 1u : 0u;
    asm volatile(
        "{\n\t.reg .pred p;\n\tsetp.ne.u32 p, %6, 0;\n\t"
        "tcgen05.mma.cta_group::2.kind::f16 [%0], %1, %2, %3, "
        "{%4, %4, %4, %4, %4, %4, %4, %4}, p;\n\t}"
        :: "r"(d), "l"(a), "l"(b), "r"(idesc), "r"(0u), "r"(0u), "r"(en) : "memory");
}
#endif // TC_PATH

// ---------------- 1) feature transpose: scalar loads (HWSZ odd), float4 stores ----
__global__ void __launch_bounds__(256) transpose_feats(
    const float* __restrict__ f0, const float* __restrict__ f1,
    const float* __restrict__ f2, const float* __restrict__ f3) {
    __shared__ float tile[32][132];
    int bl = blockIdx.z;
    int b = bl >> 2, l = bl & 3;
    const float* f = (l == 0) ? f0 : (l == 1) ? f1 : (l == 2) ? f2 : f3;
    int hw0 = blockIdx.x * 128;
    int c0 = blockIdx.y * 32;
    int tid = threadIdx.x;

    int q = tid & 31;
    int cl = tid >> 5;
    #pragma unroll
    for (int it = 0; it < 4; it++) {
        int c = cl + it * 8;
        const float* src = f + ((size_t)b * CCH + c0 + c) * HWSZ;
        #pragma unroll
        for (int j = 0; j < 4; j++) {
            int hw = hw0 + q + j * 32;
            tile[c][q + j * 32] = (hw < HWSZ) ? src[hw] : 0.0f;
        }
    }
    __syncthreads();

    int c4g = tid & 7;
    int hwl = tid >> 3;
    #pragma unroll
    for (int it = 0; it < 4; it++) {
        int hw = hwl + it * 32;
        if (hw0 + hw < HWSZ) {
            float4 v;
            v.x = tile[c4g * 4 + 0][hw];
            v.y = tile[c4g * 4 + 1][hw];
            v.z = tile[c4g * 4 + 2][hw];
            v.w = tile[c4g * 4 + 3][hw];
            *reinterpret_cast<float4*>(
                g_T + ((size_t)bl * HWSZ + hw0 + hw) * CCH + c0 + c4g * 4) = v;
        }
    }
}

// ---------------- weight-split kernels ----------------
__global__ void split_w1(const float* __restrict__ w1) {
    __shared__ float tile[32][33];
    int k0 = blockIdx.x * 32;
    int n0 = blockIdx.y * 32;
    int k = k0 + threadIdx.y;
    int p = k >> 8, c = k & 255;
    int d = c * NPTS + p;
    tile[threadIdx.y][threadIdx.x] = w1[(size_t)d * HID + n0 + threadIdx.x];
    __syncthreads();
    float v = tile[threadIdx.x][threadIdx.y];
    __nv_bfloat16 hi = __float2bfloat16(v);
    __nv_bfloat16 lo = __float2bfloat16(v - __bfloat162float(hi));
    size_t o = (size_t)(n0 + threadIdx.y) * DFEAT + k0 + threadIdx.x;
    g_w1hi[o] = hi;
    g_w1lo[o] = lo;
}

__global__ void split_w2(const float* __restrict__ w2) {
    __shared__ float tile[32][33];
    int k0 = blockIdx.x * 32;
    int n0 = blockIdx.y * 32;
    tile[threadIdx.y][threadIdx.x] = w2[(size_t)(k0 + threadIdx.y) * HID + n0 + threadIdx.x];
    __syncthreads();
    float v = tile[threadIdx.x][threadIdx.y];
    __nv_bfloat16 hi = __float2bfloat16(v);
    __nv_bfloat16 lo = __float2bfloat16(v - __bfloat162float(hi));
    size_t o = (size_t)(n0 + threadIdx.y) * HID + k0 + threadIdx.x;
    g_w2hi[o] = hi;
    g_w2lo[o] = lo;
}

__global__ void split_wcb(const float* __restrict__ wc, const float* __restrict__ wb,
                          const float* __restrict__ bc, const float* __restrict__ bb) {
    __shared__ float tile[32][33];
    int k0 = blockIdx.x * 32;
    int n0 = blockIdx.y * 32;
    int k = k0 + threadIdx.y;
    int n = n0 + threadIdx.x;
    float v = 0.0f;
    if (n < NCLS) v = wc[(size_t)k * NCLS + n];
    else if (n < NCLS + 4) v = wb[(size_t)k * 4 + (n - NCLS)];
    tile[threadIdx.y][threadIdx.x] = v;
    if (blockIdx.x == 0 && threadIdx.y == 0) {
        int j = n0 + threadIdx.x;
        g_bcb[j] = (j < NCLS) ? bc[j] : ((j < NCLS + 4) ? bb[j - NCLS] : 0.0f);
    }
    __syncthreads();
    float u = tile[threadIdx.x][threadIdx.y];
    __nv_bfloat16 hi = __float2bfloat16(u);
    __nv_bfloat16 lo = __float2bfloat16(u - __bfloat162float(hi));
    size_t o = (size_t)(n0 + threadIdx.y) * HID + k0 + threadIdx.x;
    g_wcbhi[o] = hi;
    g_wcblo[o] = lo;
}

// ---------------- multilevel ROI align, float4-vectorized, 512 threads (R12 best) ----
__global__ void __launch_bounds__(512) roi_align(const float* __restrict__ proposals) {
    int rid = blockIdx.x;
    int b = rid >> 9;
    int tid = threadIdx.x;
    int g = tid >> 6;            // point slot 0..7
    int c4 = (tid & 63) * 4;     // channel base

    float px1 = proposals[rid * 4 + 0];
    float py1 = proposals[rid * 4 + 1];
    float px2 = proposals[rid * 4 + 2];
    float py2 = proposals[rid * 4 + 3];
    float bw = px2 - px1, bh = py2 - py1;
    float area = bw * bh;
    int lvl = (area >= 1024.0f) + (area >= 4096.0f) + (area >= 16384.0f);
    float x1 = px1 - 0.5f, y1 = py1 - 0.5f;
    float binw = bw / 7.0f, binh = bh / 7.0f;

    const float* Tb = g_T + ((size_t)(b * 4 + lvl) * HWSZ) * CCH;
    size_t dbase = (size_t)rid * DFEAT;

    #pragma unroll 1
    for (int p0 = 0; p0 < NPTS; p0 += 8) {
        int p = p0 + g;
        if (p >= NPTS) break;    // warp-uniform (g constant per warp)
        int oy = p / OUTS, ox = p % OUTS;
        float ax = 0.f, ay = 0.f, az = 0.f, aw = 0.f;
        #pragma unroll
        for (int s = 0; s < 4; s++) {
            int sy = s >> 1, sx = s & 1;
            float y = y1 + ((float)oy + ((float)sy + 0.5f) * 0.5f) * binh;
            float x = x1 + ((float)ox + ((float)sx + 0.5f) * 0.5f) * binw;
            if (y < -1.0f || y > (float)HH || x < -1.0f || x > (float)WW) continue;
            float yc = fminf(fmaxf(y, 0.0f), (float)(HH - 1));
            float xc = fminf(fmaxf(x, 0.0f), (float)(WW - 1));
            float y0f = floorf(yc), x0f = floorf(xc);
            int y0 = (int)y0f, x0 = (int)x0f;
            int y1i = min(y0 + 1, HH - 1), x1i = min(x0 + 1, WW - 1);
            float ly = yc - y0f, lx = xc - x0f;
            float hy = 1.0f - ly, hx = 1.0f - lx;
            float w00 = hy * hx, w01 = hy * lx, w10 = ly * hx, w11 = ly * lx;
            float4 v00 = *reinterpret_cast<const float4*>(Tb + (size_t)(y0  * WW + x0 ) * CCH + c4);
            float4 v01 = *reinterpret_cast<const float4*>(Tb + (size_t)(y0  * WW + x1i) * CCH + c4);
            float4 v10 = *reinterpret_cast<const float4*>(Tb + (size_t)(y1i * WW + x0 ) * CCH + c4);
            float4 v11 = *reinterpret_cast<const float4*>(Tb + (size_t)(y1i * WW + x1i) * CCH + c4);
            ax = fmaf(w00, v00.x, fmaf(w01, v01.x, fmaf(w10, v10.x, fmaf(w11, v11.x, ax))));
            ay = fmaf(w00, v00.y, fmaf(w01, v01.y, fmaf(w10, v10.y, fmaf(w11, v11.y, ay))));
            az = fmaf(w00, v00.z, fmaf(w01, v01.z, fmaf(w10, v10.z, fmaf(w11, v11.z, az))));
            aw = fmaf(w00, v00.w, fmaf(w01, v01.w, fmaf(w10, v10.w, fmaf(w11, v11.w, aw))));
        }
        float r[4] = {ax * 0.25f, ay * 0.25f, az * 0.25f, aw * 0.25f};
        __nv_bfloat16 h[4], l[4];
        #pragma unroll
        for (int i = 0; i < 4; i++) {
            h[i] = __float2bfloat16(r[i]);
            l[i] = __float2bfloat16(r[i] - __bfloat162float(h[i]));
        }
        uint2 hp, lp;
        hp.x = ((uint32_t)__bfloat16_as_ushort(h[1]) << 16) | __bfloat16_as_ushort(h[0]);
        hp.y = ((uint32_t)__bfloat16_as_ushort(h[3]) << 16) | __bfloat16_as_ushort(h[2]);
        lp.x = ((uint32_t)__bfloat16_as_ushort(l[1]) << 16) | __bfloat16_as_ushort(l[0]);
        lp.y = ((uint32_t)__bfloat16_as_ushort(l[3]) << 16) | __bfloat16_as_ushort(l[2]);
        *reinterpret_cast<uint2*>(&g_Ahi[dbase + p * CCH + c4]) = hp;
        *reinterpret_cast<uint2*>(&g_Alo[dbase + p * CCH + c4]) = lp;
    }
}

// ---------------- cg2 TMA-pipelined GEMM (proven) ----------------
#define KC 64
#define ST2 4
#define STB2 49152
#define SM_TMEMP 0
#define SM2_FULL 8
#define SM2_EMPTY (8 + ST2 * 8)
#define SM_TILES 1024
#define GEMM_SMEM (SM_TILES + ST2 * STB2)

__global__ void __launch_bounds__(256) __cluster_dims__(2, 1, 1) gemm_cg2(
    const __grid_constant__ CUtensorMap tmAhi, const __grid_constant__ CUtensorMap tmAlo,
    const __grid_constant__ CUtensorMap tmBhi, const __grid_constant__ CUtensorMap tmBlo,
    const float* __restrict__ bias, int K,
    __nv_bfloat16* __restrict__ outHi, __nv_bfloat16* __restrict__ outLo, int Nfull) {
#ifdef TC_PATH
    constexpr uint32_t IDESC =
        (1u << 4) | (1u << 7) | (1u << 10) | ((128 / 8) << 17) | ((256 / 16) << 24);

    extern __shared__ char smem[];
    uint32_t sb = smem_u32(smem);
    const int tid = threadIdx.x;
    const int wid = tid >> 5, lane = tid & 31;
    const int m0 = blockIdx.x * 128;
    const int n0 = blockIdx.y * 128;
    const uint32_t rank = blockIdx.x & 1;

    if (wid == 0) TC_ALLOC_CG2(sb + SM_TMEMP, 128);
    if (tid == 0) {
        #pragma unroll
        for (int s = 0; s < ST2; s++) {
            MBAR_INIT(sb + SM2_FULL + s * 8, 1);
            MBAR_INIT(sb + SM2_EMPTY + s * 8, 1);
        }
    }
    __syncthreads();
    CLUSTER_SYNC();
    uint32_t tmem;
    asm volatile("ld.shared.b32 %0, [%1];" : "=r"(tmem) : "r"(sb + SM_TMEMP));

    const int NCH = K / KC;

    if (wid == 0) {
        uint32_t el = elect_one();
        auto issue = [&](int j) {
            int s = j % ST2;
            if (j >= ST2) MBAR_WAIT(sb + SM2_EMPTY + s * 8, ((j / ST2) - 1) & 1);
            if (el) {
                uint32_t st = sb + SM_TILES + s * STB2;
                uint32_t fb = sb + SM2_FULL + s * 8;
                if (rank == 0) MBAR_EXPECT_TX(fb, 2 * STB2);
                TMA_LD2D_CG2(st,         &tmAhi, j * KC, m0, fb);
                TMA_LD2D_CG2(st + 16384, &tmAlo, j * KC, m0, fb);
                TMA_LD2D_CG2(st + 32768, &tmBhi, j * KC, n0 + (int)rank * 64, fb);
                TMA_LD2D_CG2(st + 40960, &tmBlo, j * KC, n0 + (int)rank * 64, fb);
            }
        };
        issue(0);
        if (NCH > 1) issue(1);
        if (NCH > 2) issue(2);
        #pragma unroll 1
        for (int j = 0; j < NCH; j++) {
            if (rank == 0) {
                int s = j % ST2;
                MBAR_WAIT(sb + SM2_FULL + s * 8, (j / ST2) & 1);
                if (el) {
                    uint32_t st = sb + SM_TILES + s * STB2;
                    uint64_t adh = make_desc_sw128(st);
                    uint64_t adl = make_desc_sw128(st + 16384);
                    uint64_t bdh = make_desc_sw128(st + 32768);
                    uint64_t bdl = make_desc_sw128(st + 40960);
                    #pragma unroll
                    for (int ks = 0; ks < 4; ks++)
                        mma_f16_ss_cg2(tmem, adh + ks * 2, bdh + ks * 2, IDESC, (j > 0) || (ks > 0));
                    #pragma unroll
                    for (int ks = 0; ks < 4; ks++)
                        mma_f16_ss_cg2(tmem, adl + ks * 2, bdh + ks * 2, IDESC, true);
                    #pragma unroll
                    for (int ks = 0; ks < 4; ks++)
                        mma_f16_ss_cg2(tmem, adh + ks * 2, bdl + ks * 2, IDESC, true);
                    TC_COMMIT_MC_CG2(sb + SM2_EMPTY + s * 8, 0x3);
                }
            }
            if (j + 3 < NCH) issue(j + 3);
        }
        MBAR_WAIT(sb + SM2_EMPTY + ((NCH - 1) % ST2) * 8, ((NCH - 1) / ST2) & 1);
    }
    __syncthreads();
    TC_FENCE_AFTER();

    int m = m0 + (wid & 3) * 32 + lane;
    int colbase = (wid >> 2) * 64;
    #pragma unroll
    for (int jb = 0; jb < 2; jb++) {
        int coloff = colbase + jb * 32;
        uint32_t r[32];
        TC_LD_X32(r, tmem + coloff);
        TC_WAIT_LD();
        #pragma unroll
        for (int c = 0; c < 32; c += 2) {
            int n = n0 + coloff + c;
            float v0 = fmaxf(__uint_as_float(r[c]) + bias[n], 0.0f);
            float v1 = fmaxf(__uint_as_float(r[c + 1]) + bias[n + 1], 0.0f);
            __nv_bfloat16 h0 = __float2bfloat16(v0);
            __nv_bfloat16 h1 = __float2bfloat16(v1);
            __nv_bfloat16 l0 = __float2bfloat16(v0 - __bfloat162float(h0));
            __nv_bfloat16 l1 = __float2bfloat16(v1 - __bfloat162float(h1));
            __nv_bfloat162 hp; hp.x = h0; hp.y = h1;
            __nv_bfloat162 lp; lp.x = l0; lp.y = l1;
            *reinterpret_cast<__nv_bfloat162*>(outHi + (size_t)m * Nfull + n) = hp;
            *reinterpret_cast<__nv_bfloat162*>(outLo + (size_t)m * Nfull + n) = lp;
        }
    }

    __syncthreads();
    if (tid == 0) {
        #pragma unroll
        for (int s = 0; s < ST2; s++) {
            MBAR_INVAL(sb + SM2_FULL + s * 8);
            MBAR_INVAL(sb + SM2_EMPTY + s * 8);
        }
    }
    __syncthreads();
    if (wid == 0) {
        TC_RELINQ_CG2();
        TC_DEALLOC_CG2(tmem, 128);
    }
    CLUSTER_SYNC();
#endif
}

// ---------------- cg1 GEMM for the heads ----------------
#define ST1 3
#define STB1 65536
#define SM1_FULL 8
#define SM1_EMPTY (8 + ST1 * 8)

__global__ void __launch_bounds__(256) gemm_heads(
    const __grid_constant__ CUtensorMap tmAhi, const __grid_constant__ CUtensorMap tmAlo,
    const __grid_constant__ CUtensorMap tmBhi, const __grid_constant__ CUtensorMap tmBlo,
    const float* __restrict__ bias, int K,
    float* __restrict__ outScores, float* __restrict__ outBbox) {
#ifdef TC_PATH
    constexpr uint32_t IDESC =
        (1u << 4) | (1u << 7) | (1u << 10) | ((128 / 8) << 17) | (8u << 24);

    extern __shared__ char smem[];
    uint32_t sb = smem_u32(smem);
    const int tid = threadIdx.x;
    const int wid = tid >> 5, lane = tid & 31;
    const int m0 = blockIdx.y * 128;
    const int n0 = blockIdx.x * 128;

    if (wid == 0) TC_ALLOC(sb + SM_TMEMP, 128);
    if (tid == 0) {
        #pragma unroll
        for (int s = 0; s < ST1; s++) {
            MBAR_INIT(sb + SM1_FULL + s * 8, 1);
            MBAR_INIT(sb + SM1_EMPTY + s * 8, 1);
        }
    }
    __syncthreads();
    uint32_t tmem;
    asm volatile("ld.shared.b32 %0, [%1];" : "=r"(tmem) : "r"(sb + SM_TMEMP));

    const int NCH = K / KC;

    if (wid == 0) {
        uint32_t el = elect_one();
        auto issue = [&](int j) {
            int s = j % ST1;
            if (j >= ST1) MBAR_WAIT(sb + SM1_EMPTY + s * 8, ((j / ST1) - 1) & 1);
            if (el) {
                uint32_t st = sb + SM_TILES + s * STB1;
                uint32_t fb = sb + SM1_FULL + s * 8;
                MBAR_EXPECT_TX(fb, STB1);
                TMA_LD2D(st,         &tmAhi, j * KC, m0, fb);
                TMA_LD2D(st + 16384, &tmAlo, j * KC, m0, fb);
                TMA_LD2D(st + 32768, &tmBhi, j * KC, n0, fb);
                TMA_LD2D(st + 49152, &tmBlo, j * KC, n0, fb);
            }
        };
        issue(0);
        if (NCH > 1) issue(1);
        #pragma unroll 1
        for (int j = 0; j < NCH; j++) {
            int s = j % ST1;
            MBAR_WAIT(sb + SM1_FULL + s * 8, (j / ST1) & 1);
            if (el) {
                uint32_t st = sb + SM_TILES + s * STB1;
                uint64_t adh = make_desc_sw128(st);
                uint64_t adl = make_desc_sw128(st + 16384);
                uint64_t bdh = make_desc_sw128(st + 32768);
                uint64_t bdl = make_desc_sw128(st + 49152);
                #pragma unroll
                for (int ks = 0; ks < 4; ks++)
                    mma_f16_ss_cg1(tmem, adh + ks * 2, bdh + ks * 2, IDESC, (j > 0) || (ks > 0));
                #pragma unroll
                for (int ks = 0; ks < 4; ks++)
                    mma_f16_ss_cg1(tmem, adl + ks * 2, bdh + ks * 2, IDESC, true);
                #pragma unroll
                for (int ks = 0; ks < 4; ks++)
                    mma_f16_ss_cg1(tmem, adh + ks * 2, bdl + ks * 2, IDESC, true);
                TC_COMMIT(sb + SM1_EMPTY + s * 8);
            }
            if (j + 2 < NCH) issue(j + 2);
        }
        MBAR_WAIT(sb + SM1_EMPTY + ((NCH - 1) % ST1) * 8, ((NCH - 1) / ST1) & 1);
    }
    __syncthreads();
    TC_FENCE_AFTER();

    int m = m0 + (wid & 3) * 32 + lane;
    int colbase = (wid >> 2) * 64;
    #pragma unroll
    for (int jb = 0; jb < 2; jb++) {
        int coloff = colbase + jb * 32;
        uint32_t r[32];
        TC_LD_X32(r, tmem + coloff);
        TC_WAIT_LD();
        #pragma unroll
        for (int c = 0; c < 32; c++) {
            int n = n0 + coloff + c;
            float v = __uint_as_float(r[c]) + bias[n];
            if (n < NCLS) outScores[(size_t)m * NCLS + n] = v;
            else if (n < NCLS + 4) outBbox[(size_t)m * 4 + (n - NCLS)] = v;
        }
    }

    __syncthreads();
    if (tid == 0) {
        #pragma unroll
        for (int s = 0; s < ST1; s++) {
            MBAR_INVAL(sb + SM1_FULL + s * 8);
            MBAR_INVAL(sb + SM1_EMPTY + s * 8);
        }
    }
    __syncthreads();
    if (wid == 0) {
        TC_RELINQ();
        TC_DEALLOC(tmem, 128);
    }
#endif
}

// ---------------- host: tensormap encode ----------------
typedef CUresult (*tmEncodeFn)(CUtensorMap*, CUtensorMapDataType, cuuint32_t, void*,
                               const cuuint64_t*, const cuuint64_t*, const cuuint32_t*,
                               const cuuint32_t*, CUtensorMapInterleave, CUtensorMapSwizzle,
                               CUtensorMapL2promotion, CUtensorMapFloatOOBfill);

static void make_tm_bf16_2d(tmEncodeFn enc, CUtensorMap* tm, void* ptr,
                            uint64_t dim0, uint64_t dim1, uint32_t box1) {
    cuuint64_t dims[2] = {dim0, dim1};
    cuuint64_t strides[1] = {dim0 * 2};
    cuuint32_t box[2] = {64, box1};
    cuuint32_t es[2] = {1, 1};
    enc(tm, CU_TENSOR_MAP_DATA_TYPE_BFLOAT16, 2, ptr, dims, strides, box, es,
        CU_TENSOR_MAP_INTERLEAVE_NONE, CU_TENSOR_MAP_SWIZZLE_128B,
        CU_TENSOR_MAP_L2_PROMOTION_L2_128B, CU_TENSOR_MAP_FLOAT_OOB_FILL_NONE);
}

// ---------------- launch ----------------
extern "C" void kernel_launch(void* const* d_in, const int* in_sizes, int n_in,
                              void* d_out, int out_size) {
    const float* f0 = (const float*)d_in[0];
    const float* f1 = (const float*)d_in[1];
    const float* f2 = (const float*)d_in[2];
    const float* f3 = (const float*)d_in[3];
    const float* proposals = (const float*)d_in[4];
    const float* w1 = (const float*)d_in[5];
    const float* b1 = (const float*)d_in[6];
    const float* w2 = (const float*)d_in[7];
    const float* b2 = (const float*)d_in[8];
    const float* wc = (const float*)d_in[9];
    const float* bc = (const float*)d_in[10];
    const float* wb = (const float*)d_in[11];
    const float* bb = (const float*)d_in[12];

    float* out_scores = (float*)d_out;
    float* out_bbox = (float*)d_out + (size_t)NROIS * NCLS;

    void *gAhi, *gAlo, *gW1hi, *gW1lo, *gW2hi, *gW2lo;
    void *gH1hi, *gH1lo, *gH2hi, *gH2lo, *gWcbhi, *gWcblo, *gBcb;
    cudaGetSymbolAddress(&gAhi, g_Ahi);
    cudaGetSymbolAddress(&gAlo, g_Alo);
    cudaGetSymbolAddress(&gW1hi, g_w1hi);
    cudaGetSymbolAddress(&gW1lo, g_w1lo);
    cudaGetSymbolAddress(&gW2hi, g_w2hi);
    cudaGetSymbolAddress(&gW2lo, g_w2lo);
    cudaGetSymbolAddress(&gH1hi, g_h1hi);
    cudaGetSymbolAddress(&gH1lo, g_h1lo);
    cudaGetSymbolAddress(&gH2hi, g_h2hi);
    cudaGetSymbolAddress(&gH2lo, g_h2lo);
    cudaGetSymbolAddress(&gWcbhi, g_wcbhi);
    cudaGetSymbolAddress(&gWcblo, g_wcblo);
    cudaGetSymbolAddress(&gBcb, g_bcb);

    void* fn = nullptr;
    cudaDriverEntryPointQueryResult qr;
    cudaGetDriverEntryPoint("cuTensorMapEncodeTiled", &fn, cudaEnableDefault, &qr);
    tmEncodeFn enc = (tmEncodeFn)fn;

    CUtensorMap tAhi1, tAlo1, tBhi1, tBlo1;
    CUtensorMap tAhi2, tAlo2, tBhi2, tBlo2;
    CUtensorMap tAhi3, tAlo3, tBhi3, tBlo3;
    make_tm_bf16_2d(enc, &tAhi1, gAhi, DFEAT, NROIS, 128);
    make_tm_bf16_2d(enc, &tAlo1, gAlo, DFEAT, NROIS, 128);
    make_tm_bf16_2d(enc, &tBhi1, gW1hi, DFEAT, HID, 64);
    make_tm_bf16_2d(enc, &tBlo1, gW1lo, DFEAT, HID, 64);
    make_tm_bf16_2d(enc, &tAhi2, gH1hi, HID, NROIS, 128);
    make_tm_bf16_2d(enc, &tAlo2, gH1lo, HID, NROIS, 128);
    make_tm_bf16_2d(enc, &tBhi2, gW2hi, HID, HID, 64);
    make_tm_bf16_2d(enc, &tBlo2, gW2lo, HID, HID, 64);
    make_tm_bf16_2d(enc, &tAhi3, gH2hi, HID, NROIS, 128);
    make_tm_bf16_2d(enc, &tAlo3, gH2lo, HID, NROIS, 128);
    make_tm_bf16_2d(enc, &tBhi3, gWcbhi, HID, 128, 128);
    make_tm_bf16_2d(enc, &tBlo3, gWcblo, HID, 128, 128);

    cudaFuncSetAttribute(gemm_cg2, cudaFuncAttributeMaxDynamicSharedMemorySize, GEMM_SMEM);
    cudaFuncSetAttribute(gemm_heads, cudaFuncAttributeMaxDynamicSharedMemorySize, GEMM_SMEM);

    static cudaStream_t s_side = nullptr;
    static cudaEvent_t evFork = nullptr, evJoin = nullptr;
    if (!s_side) {
        cudaStreamCreateWithFlags(&s_side, cudaStreamNonBlocking);
        cudaEventCreateWithFlags(&evFork, cudaEventDisableTiming);
        cudaEventCreateWithFlags(&evJoin, cudaEventDisableTiming);
    }

    // fork: weight-prep chain on side stream, feature chain on main (null) stream
    cudaEventRecord(evFork, 0);
    cudaStreamWaitEvent(s_side, evFork, 0);

    split_w1<<<dim3(DFEAT / 32, HID / 32), dim3(32, 32), 0, s_side>>>(w1);
    split_w2<<<dim3(HID / 32, HID / 32), dim3(32, 32), 0, s_side>>>(w2);
    split_wcb<<<dim3(HID / 32, 4), dim3(32, 32), 0, s_side>>>(wc, wb, bc, bb);
    cudaEventRecord(evJoin, s_side);

    {
        dim3 grid((HWSZ + 127) / 128, CCH / 32, BATCH * 4);
        transpose_feats<<<grid, 256>>>(f0, f1, f2, f3);
    }
    roi_align<<<NROIS, 512>>>(proposals);

    // join: GEMMs need the split weights
    cudaStreamWaitEvent(0, evJoin, 0);

    cudaLaunchConfig_t cfg = {};
    cudaLaunchAttribute at[1];
    at[0].id = cudaLaunchAttributeClusterDimension;
    at[0].val.clusterDim = {2, 1, 1};
    cfg.attrs = at;
    cfg.numAttrs = 1;
    cfg.blockDim = dim3(256, 1, 1);
    cfg.dynamicSmemBytes = GEMM_SMEM;
    cfg.gridDim = dim3(NROIS / 128, HID / 128);

    cudaLaunchKernelEx(&cfg, gemm_cg2,
                       tAhi1, tAlo1, tBhi1, tBlo1, (const float*)b1, (int)DFEAT,
                       (__nv_bfloat16*)gH1hi, (__nv_bfloat16*)gH1lo, (int)HID);

    cudaLaunchKernelEx(&cfg, gemm_cg2,
                       tAhi2, tAlo2, tBhi2, tBlo2, (const float*)b2, (int)HID,
                       (__nv_bfloat16*)gH2hi, (__nv_bfloat16*)gH2lo, (int)HID);

    gemm_heads<<<dim3(1, NROIS / 128), 256, GEMM_SMEM>>>(
        tAhi3, tAlo3, tBhi3, tBlo3, (const float*)gBcb, HID, out_scores, out_bbox);
}